// round 9
// baseline (speedup 1.0000x reference)
#include <cuda_runtime.h>
#include <math.h>

#define NB   16
#define CINC 256
#define DIMC 32
#define HH   128
#define WW   128
#define PIX  (HH*WW)          // 16384
#define NA   192
#define NR   192
#define APIX (NA*NR)          // 36864
#define BN_EPS 1e-5f
#define RUNCAP 132

typedef unsigned long long ull;

__device__ __forceinline__ void fma2(ull& d, ull a, ull b) {
    asm("fma.rn.f32x2 %0, %1, %2, %0;" : "+l"(d) : "l"(a), "l"(b));
}
__device__ __forceinline__ ull pack2(float x) {
    ull r; asm("mov.b64 %0, {%1, %1};" : "=l"(r) : "f"(x)); return r;
}
__device__ __forceinline__ void unpack2(ull v, float& lo, float& hi) {
    asm("mov.b64 {%0, %1}, %2;" : "=f"(lo), "=f"(hi) : "l"(v));
}
__device__ __forceinline__ ull sub2(ull a, ull b) {
    ull r; asm("sub.rn.f32x2 %0, %1, %2;" : "=l"(r) : "l"(a), "l"(b)); return r;
}
__device__ __forceinline__ ull add2(ull a, ull b) {
    ull r; asm("add.rn.f32x2 %0, %1, %2;" : "=l"(r) : "l"(a), "l"(b)); return r;
}

// ---------------- device scratch ----------------
__device__ unsigned int  g_runs[(size_t)NA * HH * RUNCAP];      // [a][line][slot] = t | r<<8
__device__ int           g_nrun[NA * HH];
__device__ float         g_h1[(size_t)NB * PIX * DIMC];         // [n][p][c]
__device__ float         g_pref[(size_t)NB * HH * 129 * DIMC];  // [n][y][x+1][c]
__device__ float         g_prefy[(size_t)NB * HH * 129 * DIMC]; // [n][x][y+1][c]
__device__ float         g_acc[(size_t)NB * DIMC * NA * NR];    // [n][c][a][r]
__device__ float         g_h2[(size_t)NB * DIMC * NA * NR];
__device__ float         g_part1[512  * DIMC * 2];
__device__ float         g_part2[2304 * DIMC * 2];
__device__ float         g_part3[2304 * DIMC * 2];
__device__ float         g_scale2[DIMC], g_shift2[DIMC];
__device__ float         g_scale3[DIMC], g_shift3[DIMC];

// ---------------- conv1 (1x1, FFMA2) + BN1 partial stats --------------------
__global__ __launch_bounds__(256, 2) void k_conv1(const float* __restrict__ x,
                                                  const float* __restrict__ w1,
                                                  const float* __restrict__ b1) {
    __shared__ float sW[CINC * DIMC];
    __shared__ float sX[4][512];
    __shared__ float sS[DIMC], sQ[DIMC];

    int tid = threadIdx.x;
    int n  = blockIdx.x >> 5;
    int p0 = (blockIdx.x & 31) * 512;

    for (int i = tid; i < CINC * DIMC; i += 256) {
        int ci = i >> 5, d = i & 31;
        sW[i] = w1[d * CINC + ci];
    }
    if (tid < DIMC) { sS[tid] = 0.f; sQ[tid] = 0.f; }

    int pl = tid & 63;
    int d0 = (tid >> 6) * 8;

    ull acc2[8][4];
#pragma unroll
    for (int j = 0; j < 8; j++)
#pragma unroll
        for (int k = 0; k < 4; k++) acc2[j][k] = 0ull;

    const float* xb = x + (size_t)n * CINC * PIX + p0;

    for (int cc = 0; cc < CINC; cc += 4) {
        __syncthreads();
        for (int i = tid; i < 4 * 512; i += 256) {
            int cl = i >> 9, pp = i & 511;
            sX[cl][pp] = xb[(size_t)(cc + cl) * PIX + pp];
        }
        __syncthreads();
#pragma unroll
        for (int cl = 0; cl < 4; cl++) {
            float xv[8];
#pragma unroll
            for (int j = 0; j < 8; j++) xv[j] = sX[cl][pl + 64 * j];
            const ulonglong2* wp = (const ulonglong2*)&sW[(cc + cl) * DIMC + d0];
            ulonglong2 wA = wp[0], wB = wp[1];
#pragma unroll
            for (int j = 0; j < 8; j++) {
                ull xp = pack2(xv[j]);
                fma2(acc2[j][0], xp, wA.x);
                fma2(acc2[j][1], xp, wA.y);
                fma2(acc2[j][2], xp, wB.x);
                fma2(acc2[j][3], xp, wB.y);
            }
        }
    }

    float bia[8];
#pragma unroll
    for (int k = 0; k < 8; k++) bia[k] = b1[d0 + k];

    float* hb = g_h1 + ((size_t)n * PIX + p0) * DIMC;
    float sl[8], ql[8];
#pragma unroll
    for (int k = 0; k < 8; k++) { sl[k] = 0.f; ql[k] = 0.f; }

#pragma unroll
    for (int j = 0; j < 8; j++) {
        float vv[8];
#pragma unroll
        for (int k2 = 0; k2 < 4; k2++) {
            float lo, hi;
            unpack2(acc2[j][k2], lo, hi);
            vv[2 * k2]     = lo + bia[2 * k2];
            vv[2 * k2 + 1] = hi + bia[2 * k2 + 1];
        }
#pragma unroll
        for (int k = 0; k < 8; k++) { sl[k] += vv[k]; ql[k] += vv[k] * vv[k]; }
        float* op = hb + (size_t)(pl + 64 * j) * DIMC + d0;
        *(float4*)op       = make_float4(vv[0], vv[1], vv[2], vv[3]);
        *(float4*)(op + 4) = make_float4(vv[4], vv[5], vv[6], vv[7]);
    }
#pragma unroll
    for (int k = 0; k < 8; k++) {
        atomicAdd(&sS[d0 + k], sl[k]);
        atomicAdd(&sQ[d0 + k], ql[k]);
    }
    __syncthreads();
    if (tid < DIMC) {
        g_part1[(blockIdx.x * DIMC + tid) * 2 + 0] = sS[tid];
        g_part1[(blockIdx.x * DIMC + tid) * 2 + 1] = sQ[tid];
    }
}

// ---------------- combo: prefixes (blocks 0..511) + run lists ---------------
__global__ __launch_bounds__(256) void k_combo(const float* __restrict__ g1,
                                               const float* __restrict__ be1) {
    __shared__ float rs[8][32], rq[8][32], ssc[32], ssh[32];
    __shared__ double stc, sts;
    __shared__ int sr[256];
    __shared__ int swcnt[8], swoff[8];

    int bid = blockIdx.x;
    int tid = threadIdx.x;

    if (bid < 512) {
        int ch = tid & 31, s = tid >> 5;
        float su = 0.f, q = 0.f;
        for (int b = s; b < 512; b += 8) {
            su += g_part1[((size_t)b * DIMC + ch) * 2 + 0];
            q  += g_part1[((size_t)b * DIMC + ch) * 2 + 1];
        }
        rs[s][ch] = su; rq[s][ch] = q;
        __syncthreads();
        if (tid < 32) {
            float S = 0.f, Q = 0.f;
            for (int t = 0; t < 8; t++) { S += rs[t][ch]; Q += rq[t][ch]; }
            float cnt = (float)(NB * PIX);
            float m   = S / cnt;
            float var = Q / cnt - m * m;
            float scv = g1[ch] * rsqrtf(var + BN_EPS);
            ssc[ch] = scv;
            ssh[ch] = be1[ch] - m * scv;
        }
        __syncthreads();

        int w = s, c = ch;
        float sc = ssc[c], sh = ssh[c];
        if (bid < 256) {
            int row = bid * 8 + w;
            int n = row >> 7, y = row & 127;
            const float* hb = g_h1 + ((size_t)n * PIX + (size_t)y * WW) * DIMC + c;
            float* pb = g_pref + (size_t)row * 129 * DIMC + c;
            float sum = 0.f;
            pb[0] = 0.f;
#pragma unroll 8
            for (int x = 0; x < 128; x++) {
                float v = fmaxf(fmaf(hb[(size_t)x * DIMC], sc, sh), 0.f);
                sum += v;
                pb[(size_t)(x + 1) * DIMC] = sum;
            }
        } else {
            int idx = (bid - 256) * 8 + w;
            int n = idx >> 7, x = idx & 127;
            const float* hb = g_h1 + ((size_t)n * PIX + x) * DIMC + c;
            float* pb = g_prefy + (size_t)idx * 129 * DIMC + c;
            float sum = 0.f;
            pb[0] = 0.f;
#pragma unroll 8
            for (int y = 0; y < 128; y++) {
                float v = fmaxf(fmaf(hb[(size_t)y * WW * DIMC], sc, sh), 0.f);
                sum += v;
                pb[(size_t)(y + 1) * DIMC] = sum;
            }
        }
    } else {
        int rid = bid - 512;
        int a = rid >> 6;
        int l0 = (rid & 63) * 2;
        int grp = tid >> 7;
        int t = tid & 127;
        int line = l0 + grp;

        if (tid == 0) {
            double irho = 182.0 / 191.0;
            double th = (double)a * (3.141592653589793 / 192.0);
            stc = cos(th) / irho;
            sts = sin(th) / irho;
        }
        __syncthreads();

        bool xmode = (a >= 48 && a < 144);
        int xc = xmode ? t : line;
        int yc = xmode ? line : t;
        double v = __dadd_rn(__dmul_rn((double)(xc - 64), stc),
                             __dmul_rn((double)(yc - 64), sts));
        int r = (int)rint(v) + 96;
        r = min(max(r, 0), 191);
        sr[tid] = r;
        __syncthreads();

        int f = (t == 0) || (r != sr[tid - 1]);
        unsigned bal = __ballot_sync(0xffffffffu, f);
        int w = t >> 5, lane = t & 31;
        int pre = __popc(bal & ((1u << lane) - 1u));
        if (lane == 31) swcnt[grp * 4 + w] = __popc(bal);
        __syncthreads();
        if (t == 0) {
            int o = 0;
            for (int i = 0; i < 4; i++) { swoff[grp * 4 + i] = o; o += swcnt[grp * 4 + i]; }
            g_nrun[a * HH + line] = o;
            g_runs[((size_t)a * HH + line) * RUNCAP + o] = 128u;
        }
        __syncthreads();
        if (f) g_runs[((size_t)a * HH + line) * RUNCAP + swoff[grp * 4 + w] + pre] =
                   (unsigned)t | ((unsigned)r << 8);
    }
}

// ---------------- BN reduce (stages 2,3) -------------------------------------
__global__ void k_red(int which, int nb, float cnt,
                      const float* __restrict__ g, const float* __restrict__ be) {
    const float* part = (which == 2) ? g_part2 : g_part3;
    float* sc = (which == 2) ? g_scale2 : g_scale3;
    float* sh = (which == 2) ? g_shift2 : g_shift3;
    __shared__ float rs[8][32], rq[8][32];
    int ch = threadIdx.x & 31, s = threadIdx.x >> 5;
    float su = 0.f, q = 0.f;
    for (int b = s; b < nb; b += 8) {
        su += part[((size_t)b * DIMC + ch) * 2 + 0];
        q  += part[((size_t)b * DIMC + ch) * 2 + 1];
    }
    rs[s][ch] = su; rq[s][ch] = q;
    __syncthreads();
    if (threadIdx.x < 32) {
        float S = 0.f, Q = 0.f;
        for (int t = 0; t < 8; t++) { S += rs[t][ch]; Q += rq[t][ch]; }
        float m   = S / cnt;
        float var = Q / cnt - m * m;
        float scv = g[ch] * rsqrtf(var + BN_EPS);
        sc[ch] = scv;
        sh[ch] = be[ch] - m * scv;
    }
}

// ---------------- DHT gather: carry + packed f32x2 adds ----------------------
__global__ __launch_bounds__(512) void k_dhtg() {
    extern __shared__ float sm[];
    float*    sAcc  = sm;                                    // [4][192][20]
    float4*   sRow  = (float4*)(sm + 4 * 192 * 20);          // [2][520]
    unsigned* sRuns = (unsigned*)(sRow + 2 * 520);           // [2][528]
    int*      sNr   = (int*)(sRuns + 2 * 528);               // [2][4]

    int tid = threadIdx.x;
    int n = blockIdx.z, ch0 = blockIdx.y * 16, a0 = blockIdx.x * 4;
    bool xmode = (a0 >= 48 && a0 < 144);

    for (int i = tid; i < 4 * 192 * 20; i += 512) sAcc[i] = 0.f;

    int w = tid >> 5, lane = tid & 31;
    int ga = w >> 2, ws = w & 3;
    int rsub = lane >> 2, c4 = lane & 3;
    int slot = ws * 8 + rsub;

    const float4* prefn = (const float4*)((xmode ? g_pref : g_prefy)
                                          + (size_t)n * HH * 129 * DIMC);
    int cbase = (int)blockIdx.y * 4;
    float* accA = sAcc + ga * 192 * 20;

    float4 ra, rc;
    unsigned ru0 = 0, ru1 = 0;
    int rn = 0;
    int aa0 = tid / RUNCAP, kk0 = tid - aa0 * RUNCAP;
    int idx1 = tid + 512;
    int aa1 = idx1 / RUNCAP, kk1 = idx1 - aa1 * RUNCAP;
    int m0 = (tid >> 2) * 8 + cbase + (tid & 3);
    int m1 = 128 * 8 + cbase + tid;

    {
        ra = prefn[m0];
        if (tid < 4) rc = prefn[m1];
        ru0 = g_runs[((size_t)(a0 + aa0) * HH + 0) * RUNCAP + kk0];
        if (tid < 16) ru1 = g_runs[((size_t)(a0 + aa1) * HH + 0) * RUNCAP + kk1];
        if (tid < 4)  rn  = g_nrun[(a0 + tid) * HH + 0];
    }

    for (int line = 0; line < 128; line++) {
        int bsel = line & 1;
        float4* buf = sRow + bsel * 520;
        unsigned* rbuf = sRuns + bsel * 528;
        buf[tid] = ra;
        if (tid < 4) buf[512 + tid] = rc;
        rbuf[tid] = ru0;
        if (tid < 16) rbuf[512 + tid] = ru1;
        if (tid < 4)  sNr[bsel * 4 + tid] = rn;
        __syncthreads();

        if (line < 127) {
            const float4* src = prefn + (size_t)(line + 1) * (129 * 8);
            ra = src[m0];
            if (tid < 4) rc = src[m1];
            ru0 = g_runs[((size_t)(a0 + aa0) * HH + line + 1) * RUNCAP + kk0];
            if (tid < 16) ru1 = g_runs[((size_t)(a0 + aa1) * HH + line + 1) * RUNCAP + kk1];
            if (tid < 4)  rn  = g_nrun[(a0 + tid) * HH + line + 1];
        }

        int nrun = sNr[bsel * 4 + ga];
        const unsigned* rl = rbuf + ga * RUNCAP;
        const ulonglong2* bufu = (const ulonglong2*)buf;
        int chunk = (nrun + 31) >> 5;
        int lo = slot * chunk;
        int hi = min(lo + chunk, nrun);
        if (lo < nrun) {
            unsigned rec = rl[lo];
            ulonglong2 ps = bufu[(int)(rec & 255u) * 4 + c4];
            for (int i = lo; i < hi; i++) {
                unsigned nxt = rl[i + 1];
                int r = (rec >> 8) & 255;
                ulonglong2 pe = bufu[(int)(nxt & 255u) * 4 + c4];
                ulonglong2* ap = (ulonglong2*)(accA + r * 20 + c4 * 4);
                ulonglong2 av = *ap;
                av.x = add2(av.x, sub2(pe.x, ps.x));
                av.y = add2(av.y, sub2(pe.y, ps.y));
                *ap = av;
                ps = pe;
                rec = nxt;
            }
        }
    }
    __syncthreads();

    for (int e = tid; e < 4 * 16 * NR; e += 512) {
        int r = e % NR;
        int t2 = e / NR;
        int c = t2 & 15, ga2 = t2 >> 4;
        g_acc[(((size_t)n * DIMC + ch0 + c) * NA + (a0 + ga2)) * NR + r] =
            sAcc[(ga2 * 192 + r) * 20 + c];
    }
}

// ---------------- 3x3 conv: FFMA2, pack-once x, pipelined LDS.128 weights ---
template <int MODE>
__global__ __launch_bounds__(256, 2) void k_conv3x3(const float* __restrict__ w,
                                                    const float* __restrict__ b,
                                                    float* __restrict__ out_ext) {
    extern __shared__ float sm[];
    float* sIn = sm;                 // 32 * 360
    float* sW  = sm + 32 * 360;      // 32*9*32
    __shared__ float sS[DIMC], sQ[DIMC];

    int tid = threadIdx.x;
    if (tid < DIMC) { sS[tid] = 0.f; sQ[tid] = 0.f; }

    int n   = blockIdx.z;
    int ty0 = blockIdx.y * 16, tx0 = blockIdx.x * 16;

    for (int i = tid; i < 32 * 9 * 32; i += 256) {
        int d = i & 31; int t = (i >> 5) % 9; int cc = i / 288;
        sW[i] = w[((size_t)d * 32 + cc) * 9 + t];
    }

    // staging: thread owns (cc = tid>>3, xseg = tid&7)
    {
        int cc = tid >> 3, xseg = tid & 7;
        const float* in = (MODE == 0) ? g_acc : g_h2;
        const float* inb = in + ((size_t)n * DIMC + cc) * 192 * 192;
        float sc2 = 0.f, sh2 = 0.f;
        if (MODE == 1) { sc2 = g_scale2[cc]; sh2 = g_shift2[cc]; }
        float* sb = sIn + cc * 360;
#pragma unroll
        for (int yy = 0; yy < 18; yy++) {
            int gy = ty0 + yy - 1;
            bool yok = (unsigned)gy < 192u;
#pragma unroll
            for (int k = 0; k < 3; k++) {
                int xx = xseg + 8 * k;
                if (xx < 18) {
                    int gx = tx0 + xx - 1;
                    float v = 0.f;
                    if (yok && (unsigned)gx < 192u) {
                        v = inb[(size_t)gy * 192 + gx];
                        if (MODE == 1) v = fmaxf(fmaf(v, sc2, sh2), 0.f);
                    }
                    sb[yy * 20 + xx] = v;
                }
            }
        }
    }
    __syncthreads();

    int pg = tid & 63, d0 = (tid >> 6) * 8;
    int px = pg & 15, pyb = pg >> 4;            // rows pyb*4 .. pyb*4+3

    ull acc2[4][4];
#pragma unroll
    for (int j = 0; j < 4; j++)
#pragma unroll
        for (int k = 0; k < 4; k++) acc2[j][k] = 0ull;

    const float* ibase = &sIn[pyb * 80 + px];

    float xN[18];
#pragma unroll
    for (int rr = 0; rr < 6; rr++)
#pragma unroll
        for (int dx = 0; dx < 3; dx++) xN[rr * 3 + dx] = ibase[rr * 20 + dx];

#pragma unroll 1
    for (int cc = 0; cc < 32; cc++) {
        // pack current x once per value
        ull xp[18];
#pragma unroll
        for (int i = 0; i < 18; i++) xp[i] = pack2(xN[i]);
        // prefetch next cc's x (raw floats)
        if (cc < 31) {
            const float* ib = ibase + (cc + 1) * 360;
#pragma unroll
            for (int rr = 0; rr < 6; rr++)
#pragma unroll
                for (int dx = 0; dx < 3; dx++) xN[rr * 3 + dx] = ib[rr * 20 + dx];
        }
        // weights: 2x LDS.128 per t, software-pipelined one t ahead
        const ulonglong2* wb = (const ulonglong2*)&sW[cc * 288 + d0];
        ulonglong2 wA = wb[0], wB = wb[1];
#pragma unroll
        for (int t = 0; t < 9; t++) {
            ulonglong2 nA, nB;
            if (t < 8) { nA = wb[(t + 1) * 8]; nB = wb[(t + 1) * 8 + 1]; }
            int ky = t / 3, kx = t % 3;
#pragma unroll
            for (int j = 0; j < 4; j++) {
                ull x = xp[(j + ky) * 3 + kx];
                fma2(acc2[j][0], x, wA.x);
                fma2(acc2[j][1], x, wA.y);
                fma2(acc2[j][2], x, wB.x);
                fma2(acc2[j][3], x, wB.y);
            }
            wA = nA; wB = nB;
        }
    }

    float bia[8];
#pragma unroll
    for (int k = 0; k < 8; k++) bia[k] = b[d0 + k];

    float* outp = (MODE == 0) ? g_h2 : out_ext;
    float sl[8], ql[8];
#pragma unroll
    for (int k = 0; k < 8; k++) { sl[k] = 0.f; ql[k] = 0.f; }

#pragma unroll
    for (int j = 0; j < 4; j++) {
        int oy = ty0 + pyb * 4 + j, ox = tx0 + px;
        float vv[8];
#pragma unroll
        for (int k2 = 0; k2 < 4; k2++) {
            float lo, hi;
            unpack2(acc2[j][k2], lo, hi);
            vv[2 * k2]     = lo + bia[2 * k2];
            vv[2 * k2 + 1] = hi + bia[2 * k2 + 1];
        }
#pragma unroll
        for (int k = 0; k < 8; k++) {
            float v = vv[k];
            outp[(((size_t)n * DIMC + d0 + k) * 192 + oy) * 192 + ox] = v;
            sl[k] += v; ql[k] += v * v;
        }
    }
#pragma unroll
    for (int k = 0; k < 8; k++) {
        atomicAdd(&sS[d0 + k], sl[k]);
        atomicAdd(&sQ[d0 + k], ql[k]);
    }
    __syncthreads();
    int bid = (blockIdx.z * gridDim.y + blockIdx.y) * gridDim.x + blockIdx.x;
    float* part = (MODE == 0) ? g_part2 : g_part3;
    if (tid < DIMC) {
        part[((size_t)bid * DIMC + tid) * 2 + 0] = sS[tid];
        part[((size_t)bid * DIMC + tid) * 2 + 1] = sQ[tid];
    }
}

// ---------------- final in-place BN3 + ReLU ---------------------------------
__global__ void k_final(float* __restrict__ out) {
    size_t i = ((size_t)blockIdx.x * 256 + threadIdx.x) * 4;
    int c = (int)((i / APIX) & 31);
    float sc = g_scale3[c], sh = g_shift3[c];
    float4 v = *(float4*)(out + i);
    v.x = fmaxf(fmaf(v.x, sc, sh), 0.f);
    v.y = fmaxf(fmaf(v.y, sc, sh), 0.f);
    v.z = fmaxf(fmaf(v.z, sc, sh), 0.f);
    v.w = fmaxf(fmaf(v.w, sc, sh), 0.f);
    *(float4*)(out + i) = v;
}

// ---------------- launch -----------------------------------------------------
extern "C" void kernel_launch(void* const* d_in, const int* in_sizes, int n_in,
                              void* d_out, int out_size) {
    const float* x   = (const float*)d_in[0];
    const float* w1  = (const float*)d_in[1];
    const float* b1  = (const float*)d_in[2];
    const float* g1  = (const float*)d_in[3];
    const float* be1 = (const float*)d_in[4];
    const float* w2  = (const float*)d_in[5];
    const float* b2  = (const float*)d_in[6];
    const float* g2  = (const float*)d_in[7];
    const float* be2 = (const float*)d_in[8];
    const float* w3  = (const float*)d_in[9];
    const float* b3  = (const float*)d_in[10];
    const float* g3  = (const float*)d_in[11];
    const float* be3 = (const float*)d_in[12];
    float* out = (float*)d_out;

    const int dhtSmem  = 4 * 192 * 20 * 4 + 2 * 520 * 16 + 2 * 528 * 4 + 8 * 4; // 82336
    const int convSmem = (32 * 360 + 32 * 9 * 32) * 4;                          // 82944
    cudaFuncSetAttribute(k_dhtg,       cudaFuncAttributeMaxDynamicSharedMemorySize, dhtSmem);
    cudaFuncSetAttribute(k_conv3x3<0>, cudaFuncAttributeMaxDynamicSharedMemorySize, convSmem);
    cudaFuncSetAttribute(k_conv3x3<1>, cudaFuncAttributeMaxDynamicSharedMemorySize, convSmem);

    // conv3x3<0> stays at launch index 3 (profiled slot)
    k_conv1<<<512, 256>>>(x, w1, b1);
    k_combo<<<512 + NA * 64, 256>>>(g1, be1);
    k_dhtg<<<dim3(48, 2, NB), 512, dhtSmem>>>();

    dim3 cgrid(12, 12, NB);
    k_conv3x3<0><<<cgrid, 256, convSmem>>>(w2, b2, nullptr);
    k_red<<<1, 256>>>(2, 2304, (float)(NB * APIX), g2, be2);

    k_conv3x3<1><<<cgrid, 256, convSmem>>>(w3, b3, out);
    k_red<<<1, 256>>>(3, 2304, (float)(NB * APIX), g3, be3);

    k_final<<<(NB * DIMC * APIX) / (256 * 4), 256>>>(out);
}

// round 11
// speedup vs baseline: 1.5573x; 1.5573x over previous
#include <cuda_runtime.h>
#include <cuda_bf16.h>
#include <math.h>
#include <cstdint>

#define NB   16
#define CINC 256
#define DIMC 32
#define HH   128
#define WW   128
#define PIX  (HH*WW)
#define NA   192
#define NR   192
#define APIX (NA*NR)
#define BN_EPS 1e-5f
#define RUNCAP 132

typedef unsigned long long ull;

// ---------------- fp32x2 helpers ----------------
__device__ __forceinline__ void fma2(ull& d, ull a, ull b) {
    asm("fma.rn.f32x2 %0, %1, %2, %0;" : "+l"(d) : "l"(a), "l"(b));
}
__device__ __forceinline__ ull pack2(float x) {
    ull r; asm("mov.b64 %0, {%1, %1};" : "=l"(r) : "f"(x)); return r;
}
__device__ __forceinline__ void unpack2(ull v, float& lo, float& hi) {
    asm("mov.b64 {%0, %1}, %2;" : "=f"(lo), "=f"(hi) : "l"(v));
}

// ---------------- HMMA: mma.sync m16n8k16 bf16 (baseline PTX, sm_80+) --------
__device__ __forceinline__ void mma_bf16(float* d, const uint32_t* a, const uint32_t* b) {
    asm volatile(
        "mma.sync.aligned.m16n8k16.row.col.f32.bf16.bf16.f32 "
        "{%0,%1,%2,%3}, {%4,%5,%6,%7}, {%8,%9}, {%0,%1,%2,%3};"
        : "+f"(d[0]), "+f"(d[1]), "+f"(d[2]), "+f"(d[3])
        : "r"(a[0]), "r"(a[1]), "r"(a[2]), "r"(a[3]), "r"(b[0]), "r"(b[1]));
}

// ---------------- device scratch ----------------
__device__ unsigned int  g_runs[(size_t)NA * HH * RUNCAP];
__device__ int           g_nrun[NA * HH];
__device__ float         g_h1[(size_t)NB * PIX * DIMC];
__device__ float         g_pref[(size_t)NB * HH * 129 * DIMC];
__device__ float         g_prefy[(size_t)NB * HH * 129 * DIMC];
__device__ float         g_acc[(size_t)NB * DIMC * NA * NR];
__device__ float         g_h2[(size_t)NB * DIMC * NA * NR];
__device__ float         g_part1[512 * DIMC * 2];
__device__ float         g_part2[512 * 2 * 2];
__device__ float         g_scale2[DIMC], g_shift2[DIMC];
__device__ float         g_scale3[DIMC], g_shift3[DIMC];

// ---------------- conv1 (1x1, FFMA2) + BN1 partial stats --------------------
__global__ __launch_bounds__(256, 2) void k_conv1(const float* __restrict__ x,
                                                  const float* __restrict__ w1,
                                                  const float* __restrict__ b1) {
    __shared__ float sW[CINC * DIMC];
    __shared__ float sX[4][512];
    __shared__ float sS[DIMC], sQ[DIMC];

    int tid = threadIdx.x;
    int n  = blockIdx.x >> 5;
    int p0 = (blockIdx.x & 31) * 512;

    for (int i = tid; i < CINC * DIMC; i += 256) {
        int ci = i >> 5, d = i & 31;
        sW[i] = w1[d * CINC + ci];
    }
    if (tid < DIMC) { sS[tid] = 0.f; sQ[tid] = 0.f; }

    int pl = tid & 63;
    int d0 = (tid >> 6) * 8;

    ull acc2[8][4];
#pragma unroll
    for (int j = 0; j < 8; j++)
#pragma unroll
        for (int k = 0; k < 4; k++) acc2[j][k] = 0ull;

    const float* xb = x + (size_t)n * CINC * PIX + p0;

    for (int cc = 0; cc < CINC; cc += 4) {
        __syncthreads();
        for (int i = tid; i < 4 * 512; i += 256) {
            int cl = i >> 9, pp = i & 511;
            sX[cl][pp] = xb[(size_t)(cc + cl) * PIX + pp];
        }
        __syncthreads();
#pragma unroll
        for (int cl = 0; cl < 4; cl++) {
            float xv[8];
#pragma unroll
            for (int j = 0; j < 8; j++) xv[j] = sX[cl][pl + 64 * j];
            const ull* wp = (const ull*)&sW[(cc + cl) * DIMC + d0];
            ull w0 = wp[0], w1r = wp[1], w2 = wp[2], w3 = wp[3];
#pragma unroll
            for (int j = 0; j < 8; j++) {
                ull xp = pack2(xv[j]);
                fma2(acc2[j][0], xp, w0);
                fma2(acc2[j][1], xp, w1r);
                fma2(acc2[j][2], xp, w2);
                fma2(acc2[j][3], xp, w3);
            }
        }
    }

    float bia[8];
#pragma unroll
    for (int k = 0; k < 8; k++) bia[k] = b1[d0 + k];

    float* hb = g_h1 + ((size_t)n * PIX + p0) * DIMC;
    float sl[8], ql[8];
#pragma unroll
    for (int k = 0; k < 8; k++) { sl[k] = 0.f; ql[k] = 0.f; }

#pragma unroll
    for (int j = 0; j < 8; j++) {
        float vv[8];
#pragma unroll
        for (int k2 = 0; k2 < 4; k2++) {
            float lo, hi;
            unpack2(acc2[j][k2], lo, hi);
            vv[2 * k2]     = lo + bia[2 * k2];
            vv[2 * k2 + 1] = hi + bia[2 * k2 + 1];
        }
#pragma unroll
        for (int k = 0; k < 8; k++) { sl[k] += vv[k]; ql[k] += vv[k] * vv[k]; }
        float* op = hb + (size_t)(pl + 64 * j) * DIMC + d0;
        *(float4*)op       = make_float4(vv[0], vv[1], vv[2], vv[3]);
        *(float4*)(op + 4) = make_float4(vv[4], vv[5], vv[6], vv[7]);
    }
#pragma unroll
    for (int k = 0; k < 8; k++) {
        atomicAdd(&sS[d0 + k], sl[k]);
        atomicAdd(&sQ[d0 + k], ql[k]);
    }
    __syncthreads();
    if (tid < DIMC) {
        g_part1[(blockIdx.x * DIMC + tid) * 2 + 0] = sS[tid];
        g_part1[(blockIdx.x * DIMC + tid) * 2 + 1] = sQ[tid];
    }
}

// ---------------- combo: prefixes + run lists --------------------------------
__global__ __launch_bounds__(256) void k_combo(const float* __restrict__ g1,
                                               const float* __restrict__ be1) {
    __shared__ float rs[8][32], rq[8][32], ssc[32], ssh[32];
    __shared__ double stc, sts;
    __shared__ int sr[256];
    __shared__ int swcnt[8], swoff[8];

    int bid = blockIdx.x;
    int tid = threadIdx.x;

    if (bid < 512) {
        int ch = tid & 31, s = tid >> 5;
        float su = 0.f, q = 0.f;
        for (int b = s; b < 512; b += 8) {
            su += g_part1[((size_t)b * DIMC + ch) * 2 + 0];
            q  += g_part1[((size_t)b * DIMC + ch) * 2 + 1];
        }
        rs[s][ch] = su; rq[s][ch] = q;
        __syncthreads();
        if (tid < 32) {
            float S = 0.f, Q = 0.f;
            for (int t = 0; t < 8; t++) { S += rs[t][ch]; Q += rq[t][ch]; }
            float cnt = (float)(NB * PIX);
            float m   = S / cnt;
            float var = Q / cnt - m * m;
            float scv = g1[ch] * rsqrtf(var + BN_EPS);
            ssc[ch] = scv;
            ssh[ch] = be1[ch] - m * scv;
        }
        __syncthreads();

        int w = s, c = ch;
        float sc = ssc[c], sh = ssh[c];
        if (bid < 256) {
            int row = bid * 8 + w;
            int n = row >> 7, y = row & 127;
            const float* hb = g_h1 + ((size_t)n * PIX + (size_t)y * WW) * DIMC + c;
            float* pb = g_pref + (size_t)row * 129 * DIMC + c;
            float sum = 0.f;
            pb[0] = 0.f;
#pragma unroll 8
            for (int x = 0; x < 128; x++) {
                float v = fmaxf(fmaf(hb[(size_t)x * DIMC], sc, sh), 0.f);
                sum += v;
                pb[(size_t)(x + 1) * DIMC] = sum;
            }
        } else {
            int idx = (bid - 256) * 8 + w;
            int n = idx >> 7, x = idx & 127;
            const float* hb = g_h1 + ((size_t)n * PIX + x) * DIMC + c;
            float* pb = g_prefy + (size_t)idx * 129 * DIMC + c;
            float sum = 0.f;
            pb[0] = 0.f;
#pragma unroll 8
            for (int y = 0; y < 128; y++) {
                float v = fmaxf(fmaf(hb[(size_t)y * WW * DIMC], sc, sh), 0.f);
                sum += v;
                pb[(size_t)(y + 1) * DIMC] = sum;
            }
        }
    } else {
        int rid = bid - 512;
        int a = rid >> 6;
        int l0 = (rid & 63) * 2;
        int grp = tid >> 7;
        int t = tid & 127;
        int line = l0 + grp;

        if (tid == 0) {
            double irho = 182.0 / 191.0;
            double th = (double)a * (3.141592653589793 / 192.0);
            stc = cos(th) / irho;
            sts = sin(th) / irho;
        }
        __syncthreads();

        bool xmode = (a >= 48 && a < 144);
        int xc = xmode ? t : line;
        int yc = xmode ? line : t;
        double v = __dadd_rn(__dmul_rn((double)(xc - 64), stc),
                             __dmul_rn((double)(yc - 64), sts));
        int r = (int)rint(v) + 96;
        r = min(max(r, 0), 191);
        sr[tid] = r;
        __syncthreads();

        int f = (t == 0) || (r != sr[tid - 1]);
        unsigned bal = __ballot_sync(0xffffffffu, f);
        int w = t >> 5, lane = t & 31;
        int pre = __popc(bal & ((1u << lane) - 1u));
        if (lane == 31) swcnt[grp * 4 + w] = __popc(bal);
        __syncthreads();
        if (t == 0) {
            int o = 0;
            for (int i = 0; i < 4; i++) { swoff[grp * 4 + i] = o; o += swcnt[grp * 4 + i]; }
            g_nrun[a * HH + line] = o;
            g_runs[((size_t)a * HH + line) * RUNCAP + o] = 128u;
        }
        __syncthreads();
        if (f) g_runs[((size_t)a * HH + line) * RUNCAP + swoff[grp * 4 + w] + pre] =
                   (unsigned)t | ((unsigned)r << 8);
    }
}

// ---------------- DHT gather (R7 proven version) ------------------------------
__global__ __launch_bounds__(512) void k_dhtg() {
    extern __shared__ float sm[];
    float*    sAcc  = sm;
    float4*   sRow  = (float4*)(sm + 4 * 192 * 20);
    unsigned* sRuns = (unsigned*)(sRow + 2 * 520);
    int*      sNr   = (int*)(sRuns + 2 * 528);

    int tid = threadIdx.x;
    int n = blockIdx.z, ch0 = blockIdx.y * 16, a0 = blockIdx.x * 4;
    bool xmode = (a0 >= 48 && a0 < 144);

    for (int i = tid; i < 4 * 192 * 20; i += 512) sAcc[i] = 0.f;

    int w = tid >> 5, lane = tid & 31;
    int ga = w >> 2, ws = w & 3;
    int rsub = lane >> 2, c4 = lane & 3;
    int slot = ws * 8 + rsub;

    const float4* prefn = (const float4*)((xmode ? g_pref : g_prefy)
                                          + (size_t)n * HH * 129 * DIMC);
    int cbase = (int)blockIdx.y * 4;
    float* accA = sAcc + ga * 192 * 20;

    float4 ra, rc;
    unsigned ru0 = 0, ru1 = 0;
    int rn = 0;
    int aa0 = tid / RUNCAP, kk0 = tid - aa0 * RUNCAP;
    int idx1 = tid + 512;
    int aa1 = idx1 / RUNCAP, kk1 = idx1 - aa1 * RUNCAP;
    int m0 = (tid >> 2) * 8 + cbase + (tid & 3);
    int m1 = 128 * 8 + cbase + tid;

    {
        ra = prefn[m0];
        if (tid < 4) rc = prefn[m1];
        ru0 = g_runs[((size_t)(a0 + aa0) * HH + 0) * RUNCAP + kk0];
        if (tid < 16) ru1 = g_runs[((size_t)(a0 + aa1) * HH + 0) * RUNCAP + kk1];
        if (tid < 4)  rn  = g_nrun[(a0 + tid) * HH + 0];
    }

    for (int line = 0; line < 128; line++) {
        int bsel = line & 1;
        float4* buf = sRow + bsel * 520;
        unsigned* rbuf = sRuns + bsel * 528;
        buf[tid] = ra;
        if (tid < 4) buf[512 + tid] = rc;
        rbuf[tid] = ru0;
        if (tid < 16) rbuf[512 + tid] = ru1;
        if (tid < 4)  sNr[bsel * 4 + tid] = rn;
        __syncthreads();

        if (line < 127) {
            const float4* src = prefn + (size_t)(line + 1) * (129 * 8);
            ra = src[m0];
            if (tid < 4) rc = src[m1];
            ru0 = g_runs[((size_t)(a0 + aa0) * HH + line + 1) * RUNCAP + kk0];
            if (tid < 16) ru1 = g_runs[((size_t)(a0 + aa1) * HH + line + 1) * RUNCAP + kk1];
            if (tid < 4)  rn  = g_nrun[(a0 + tid) * HH + line + 1];
        }

        int nrun = sNr[bsel * 4 + ga];
        const unsigned* rl = rbuf + ga * RUNCAP;
        int chunk = (nrun + 31) >> 5;
        int lo = slot * chunk;
        int hi = min(lo + chunk, nrun);
        if (lo < nrun) {
            float4 ps = buf[(int)(rl[lo] & 255u) * 4 + c4];
            for (int i = lo; i < hi; i++) {
                unsigned rec = rl[i];
                int r  = (rec >> 8) & 255;
                int xe = (int)(rl[i + 1] & 255u);
                float4 pe = buf[xe * 4 + c4];
                float* ap = accA + r * 20 + c4 * 4;
                float4 av = *(float4*)ap;
                av.x += pe.x - ps.x; av.y += pe.y - ps.y;
                av.z += pe.z - ps.z; av.w += pe.w - ps.w;
                *(float4*)ap = av;
                ps = pe;
            }
        }
    }
    __syncthreads();

    for (int e = tid; e < 4 * 16 * NR; e += 512) {
        int r = e % NR;
        int t2 = e / NR;
        int c = t2 & 15, ga2 = t2 >> 4;
        g_acc[(((size_t)n * DIMC + ch0 + c) * NA + (a0 + ga2)) * NR + r] =
            sAcc[(ga2 * 192 + r) * 20 + c];
    }
}

// ---------------- HMMA 3x3 conv (bf16 split-2 implicit GEMM) -----------------
// Block: 16x16 px tile, all 32 d. 8 warps; warp = 2 pixel-rows x 32 d.
// smem: bias[32] @0; Whi @128 (32x296 bf16), Wlo @19072; haloHi @38016
//       (324 px x 40 bf16), haloLo @63936. total 89856.
#define MM_SMEM 89856
#define WPITCH  296
#define HPITCH  40
template <int MODE>
__global__ __launch_bounds__(256) void k_mma(const float* __restrict__ w,
                                             const float* __restrict__ bias,
                                             float* __restrict__ out_ext) {
    extern __shared__ char smem[];
    __shared__ float sSc[32], sSh[32];
    float*        sBias = (float*)smem;
    __nv_bfloat16* sWh = (__nv_bfloat16*)(smem + 128);
    __nv_bfloat16* sWl = (__nv_bfloat16*)(smem + 19072);
    __nv_bfloat16* sHi = (__nv_bfloat16*)(smem + 38016);
    __nv_bfloat16* sLo = (__nv_bfloat16*)(smem + 63936);

    int tid = threadIdx.x;
    int n = blockIdx.z;
    int ty0 = blockIdx.y * 16, tx0 = blockIdx.x * 16;

    if (tid < 32) {
        sBias[tid] = bias[tid];
        if (MODE == 1) { sSc[tid] = g_scale2[tid]; sSh[tid] = g_shift2[tid]; }
    }

    // weights: k = t*32 + cc ; row pitch 296
    for (int i = tid; i < 32 * 288; i += 256) {
        int d = i / 288, kk = i - d * 288;
        int cc = kk & 31, t = kk >> 5;
        float v = w[((size_t)d * 32 + cc) * 9 + t];
        __nv_bfloat16 h = __float2bfloat16(v);
        __nv_bfloat16 l = __float2bfloat16(v - __bfloat162float(h));
        sWh[d * WPITCH + t * 32 + cc] = h;
        sWl[d * WPITCH + t * 32 + cc] = l;
    }
    __syncthreads();   // MODE==1 needs sSc before halo staging

    // halo: 18x18 px, channel-contiguous, pitch 40
    const float* in = (MODE == 0) ? g_acc : g_h2;
    const float* inb = in + (size_t)n * 32 * APIX;
    for (int i = tid; i < 324 * 32; i += 256) {
        int cc = i / 324, rem = i - cc * 324;
        int y = rem / 18, x = rem - y * 18;
        int gy = ty0 + y - 1, gx = tx0 + x - 1;
        float v = 0.f;
        if ((unsigned)gy < 192u && (unsigned)gx < 192u) {
            v = inb[((size_t)cc * 192 + gy) * 192 + gx];
            if (MODE == 1) v = fmaxf(fmaf(v, sSc[cc], sSh[cc]), 0.f);
        }
        __nv_bfloat16 h = __float2bfloat16(v);
        __nv_bfloat16 l = __float2bfloat16(v - __bfloat162float(h));
        int hp = y * 18 + x;
        sHi[hp * HPITCH + cc] = h;
        sLo[hp * HPITCH + cc] = l;
    }
    __syncthreads();

    int wrp = tid >> 5, lane = tid & 31;
    int gid = lane >> 2, qid = lane & 3;
    int pyr = 2 * wrp;                       // warp rows pyr, pyr+1

    float acc[2][4][4];
#pragma unroll
    for (int m = 0; m < 2; m++)
#pragma unroll
        for (int nt = 0; nt < 4; nt++)
#pragma unroll
            for (int j = 0; j < 4; j++) acc[m][nt][j] = 0.f;

#pragma unroll 1
    for (int s = 0; s < 18; s++) {
        int t = s >> 1, kh = s & 1;
        int ky = t / 3, kx = t - ky * 3;
        int cb = kh * 16 + qid * 2;

        uint32_t Ah[2][4], Al[2][4];
#pragma unroll
        for (int m = 0; m < 2; m++) {
            int hpb = (pyr + m + ky) * 18 + kx + gid;
            int o0 = hpb * HPITCH + cb;
            int o1 = (hpb + 8) * HPITCH + cb;
            Ah[m][0] = *(const uint32_t*)&sHi[o0];
            Ah[m][1] = *(const uint32_t*)&sHi[o1];
            Ah[m][2] = *(const uint32_t*)&sHi[o0 + 8];
            Ah[m][3] = *(const uint32_t*)&sHi[o1 + 8];
            Al[m][0] = *(const uint32_t*)&sLo[o0];
            Al[m][1] = *(const uint32_t*)&sLo[o1];
            Al[m][2] = *(const uint32_t*)&sLo[o0 + 8];
            Al[m][3] = *(const uint32_t*)&sLo[o1 + 8];
        }
        int kb = t * 32 + cb;
#pragma unroll
        for (int nt = 0; nt < 4; nt++) {
            int d = nt * 8 + gid;
            uint32_t bh[2], bl[2];
            bh[0] = *(const uint32_t*)&sWh[d * WPITCH + kb];
            bh[1] = *(const uint32_t*)&sWh[d * WPITCH + kb + 8];
            bl[0] = *(const uint32_t*)&sWl[d * WPITCH + kb];
            bl[1] = *(const uint32_t*)&sWl[d * WPITCH + kb + 8];
            mma_bf16(acc[0][nt], Ah[0], bh);
            mma_bf16(acc[0][nt], Ah[0], bl);
            mma_bf16(acc[0][nt], Al[0], bh);
            mma_bf16(acc[1][nt], Ah[1], bh);
            mma_bf16(acc[1][nt], Ah[1], bl);
            mma_bf16(acc[1][nt], Al[1], bh);
        }
    }

    // epilogue: D row = px = gid(+8); D col = channel = nt*8 + qid*2 + (j&1)
    float* op = (MODE == 0) ? g_h2 : out_ext;
    float* ob = op + (size_t)n * 32 * APIX;
#pragma unroll
    for (int m = 0; m < 2; m++) {
        int py = ty0 + pyr + m;
#pragma unroll
        for (int nt = 0; nt < 4; nt++) {
#pragma unroll
            for (int j = 0; j < 4; j++) {
                int d = nt * 8 + qid * 2 + (j & 1);
                int px = tx0 + gid + ((j >> 1) * 8);
                ob[(size_t)d * APIX + (size_t)py * 192 + px] = acc[m][nt][j] + sBias[d];
            }
        }
    }
}

// ---------------- per-(d,n) stats over [n][d][APIX] --------------------------
__global__ __launch_bounds__(256) void k_stats(int which, const float* __restrict__ ext) {
    __shared__ float ss[8], sq[8];
    int d = blockIdx.x, n = blockIdx.y, tid = threadIdx.x;
    const float* src = (which == 2) ? g_h2 : ext;
    const float4* p = (const float4*)(src + ((size_t)n * 32 + d) * APIX);
    float s = 0.f, q = 0.f;
    for (int i = tid; i < APIX / 4; i += 256) {
        float4 v = p[i];
        s += v.x + v.y + v.z + v.w;
        q += v.x * v.x + v.y * v.y + v.z * v.z + v.w * v.w;
    }
#pragma unroll
    for (int o = 16; o; o >>= 1) {
        s += __shfl_xor_sync(0xffffffffu, s, o);
        q += __shfl_xor_sync(0xffffffffu, q, o);
    }
    if ((tid & 31) == 0) { ss[tid >> 5] = s; sq[tid >> 5] = q; }
    __syncthreads();
    if (tid == 0) {
        float S = 0.f, Q = 0.f;
        for (int i = 0; i < 8; i++) { S += ss[i]; Q += sq[i]; }
        g_part2[(d * 16 + n) * 2 + 0] = S;
        g_part2[(d * 16 + n) * 2 + 1] = Q;
    }
}

__global__ void k_red2(int which, const float* __restrict__ g,
                       const float* __restrict__ be) {
    int d = threadIdx.x;
    if (d < 32) {
        float S = 0.f, Q = 0.f;
        for (int n2 = 0; n2 < 16; n2++) {
            S += g_part2[(d * 16 + n2) * 2 + 0];
            Q += g_part2[(d * 16 + n2) * 2 + 1];
        }
        float cnt = (float)NB * (float)APIX;
        float m = S / cnt;
        float var = Q / cnt - m * m;
        float sc = g[d] * rsqrtf(var + BN_EPS);
        if (which == 2) { g_scale2[d] = sc; g_shift2[d] = be[d] - m * sc; }
        else            { g_scale3[d] = sc; g_shift3[d] = be[d] - m * sc; }
    }
}

// ---------------- final in-place BN3 + ReLU ---------------------------------
__global__ void k_final(float* __restrict__ out) {
    size_t i = ((size_t)blockIdx.x * 256 + threadIdx.x) * 4;
    int c = (int)((i / APIX) & 31);
    float sc = g_scale3[c], sh = g_shift3[c];
    float4 v = *(float4*)(out + i);
    v.x = fmaxf(fmaf(v.x, sc, sh), 0.f);
    v.y = fmaxf(fmaf(v.y, sc, sh), 0.f);
    v.z = fmaxf(fmaf(v.z, sc, sh), 0.f);
    v.w = fmaxf(fmaf(v.w, sc, sh), 0.f);
    *(float4*)(out + i) = v;
}

// ---------------- launch -----------------------------------------------------
extern "C" void kernel_launch(void* const* d_in, const int* in_sizes, int n_in,
                              void* d_out, int out_size) {
    const float* x   = (const float*)d_in[0];
    const float* w1  = (const float*)d_in[1];
    const float* b1  = (const float*)d_in[2];
    const float* g1  = (const float*)d_in[3];
    const float* be1 = (const float*)d_in[4];
    const float* w2  = (const float*)d_in[5];
    const float* b2  = (const float*)d_in[6];
    const float* g2  = (const float*)d_in[7];
    const float* be2 = (const float*)d_in[8];
    const float* w3  = (const float*)d_in[9];
    const float* b3  = (const float*)d_in[10];
    const float* g3  = (const float*)d_in[11];
    const float* be3 = (const float*)d_in[12];
    float* out = (float*)d_out;

    const int dhtSmem = 4 * 192 * 20 * 4 + 2 * 520 * 16 + 2 * 528 * 4 + 8 * 4; // 82336
    cudaFuncSetAttribute(k_dhtg,   cudaFuncAttributeMaxDynamicSharedMemorySize, dhtSmem);
    cudaFuncSetAttribute(k_mma<0>, cudaFuncAttributeMaxDynamicSharedMemorySize, MM_SMEM);
    cudaFuncSetAttribute(k_mma<1>, cudaFuncAttributeMaxDynamicSharedMemorySize, MM_SMEM);

    // k_mma<0> at launch index 3 (profiled slot)
    k_conv1<<<512, 256>>>(x, w1, b1);
    k_combo<<<512 + NA * 64, 256>>>(g1, be1);
    k_dhtg<<<dim3(48, 2, NB), 512, dhtSmem>>>();

    dim3 cgrid(12, 12, NB);
    k_mma<0><<<cgrid, 256, MM_SMEM>>>(w2, b2, nullptr);
    k_stats<<<dim3(32, 16), 256>>>(2, nullptr);
    k_red2<<<1, 32>>>(2, g2, be2);

    k_mma<1><<<cgrid, 256, MM_SMEM>>>(w3, b3, out);
    k_stats<<<dim3(32, 16), 256>>>(3, out);
    k_red2<<<1, 32>>>(3, g3, be3);

    k_final<<<(NB * DIMC * APIX) / (256 * 4), 256>>>(out);
}